// round 4
// baseline (speedup 1.0000x reference)
#include <cuda_runtime.h>

#define G   128
#define F   16
#define NX  100
#define NY  100
#define NZ  8
#define NPTS (NX*NY*NZ)

#define TX  4
#define TY  10
#define TZ  8
#define TPB (TX*TY*TZ)   // 320

__global__ __launch_bounds__(TPB)
void fused_splat_kernel(const float* __restrict__ means,
                        const float* __restrict__ opac,
                        const float* __restrict__ feats,
                        const float* __restrict__ covs,
                        float* __restrict__ out) {
    __shared__ float s_mu[G][3];
    __shared__ float s_hw[G][3];    // ellipsoid AABB half-widths: 2*sqrt(C_ii)
    __shared__ float s_ic[G][6];
    __shared__ float s_opac[G];
    __shared__ float s_of[G][F];
    __shared__ unsigned s_wm[4];    // per-warp survivor ballots (warps 0..3)

    const int tid = threadIdx.x;
    const int bx  = blockIdx.x;     // 0..24 (x tiles of 4)
    const int by  = blockIdx.y;     // 0..9  (y tiles of 10)

    // Tile AABB over voxel centers
    const float x0 = (bx*TX + 0.5f) * 0.8f - 40.0f;
    const float x1 = (bx*TX + TX - 0.5f) * 0.8f - 40.0f;
    const float y0 = (by*TY + 0.5f) * 0.8f - 40.0f;
    const float y1 = (by*TY + TY - 0.5f) * 0.8f - 40.0f;
    const float z0 = 0.5f * 0.8f - 1.0f;
    const float z1 = (NZ - 0.5f) * 0.8f - 1.0f;

    // ── Stage 1a: per-axis ellipsoid-AABB cull (threads 0..127 = 4 full warps) ──
    // maha<=4 region is an ellipsoid; its AABB half-width on axis i is 2*sqrt(C_ii).
    bool keep = false;
    float mx, my, mz, hwx, hwy, hwz;
    if (tid < G) {
        const int g = tid;
        mx = means[g*3 + 0];
        my = means[g*3 + 1];
        mz = means[g*3 + 2];
        hwx = 2.0f * sqrtf(covs[g*9 + 0]) * 1.0002f + 1e-3f;
        hwy = 2.0f * sqrtf(covs[g*9 + 4]) * 1.0002f + 1e-3f;
        hwz = 2.0f * sqrtf(covs[g*9 + 8]) * 1.0002f + 1e-3f;
        const float cx = fabsf(fminf(fmaxf(mx, x0), x1) - mx);
        const float cy = fabsf(fminf(fmaxf(my, y0), y1) - my);
        const float cz = fabsf(fminf(fmaxf(mz, z0), z1) - mz);
        keep = (cx <= hwx) && (cy <= hwy) && (cz <= hwz);
        const unsigned m = __ballot_sync(0xffffffffu, keep);
        if ((tid & 31) == 0) s_wm[tid >> 5] = m;
    }
    __syncthreads();

    // ── Stage 1b: deterministic compaction (ascending g) + per-survivor prep ──
    if (keep) {
        const int g = tid;
        const int w = tid >> 5, lane = tid & 31;
        int k = __popc(s_wm[w] & ((1u << lane) - 1u));
        #pragma unroll
        for (int i = 0; i < 4; i++) if (i < w) k += __popc(s_wm[i]);

        // 3x3 symmetric inverse in double
        const float* C = covs + g*9;
        double m00 = C[0], m01 = C[1], m02 = C[2];
        double m10 = C[3], m11 = C[4], m12 = C[5];
        double m20 = C[6], m21 = C[7], m22 = C[8];
        double A00 = m11*m22 - m12*m21;
        double A01 = m02*m21 - m01*m22;
        double A02 = m01*m12 - m02*m11;
        double A10 = m12*m20 - m10*m22;
        double A11 = m00*m22 - m02*m20;
        double A12 = m02*m10 - m00*m12;
        double A20 = m10*m21 - m11*m20;
        double A21 = m01*m20 - m00*m21;
        double A22 = m00*m11 - m01*m10;
        double det = m00*A00 + m01*A10 + m02*A20;
        double id  = 1.0 / det;

        s_ic[k][0] = (float)(A00 * id);
        s_ic[k][1] = (float)(0.5 * (A01 + A10) * id);
        s_ic[k][2] = (float)(0.5 * (A02 + A20) * id);
        s_ic[k][3] = (float)(A11 * id);
        s_ic[k][4] = (float)(0.5 * (A12 + A21) * id);
        s_ic[k][5] = (float)(A22 * id);

        s_mu[k][0] = mx;  s_mu[k][1] = my;  s_mu[k][2] = mz;
        s_hw[k][0] = hwx; s_hw[k][1] = hwy; s_hw[k][2] = hwz;
        const float o = opac[g];
        s_opac[k] = o;
        #pragma unroll
        for (int j = 0; j < F; j++) s_of[k][j] = o * feats[g*F + j];
    }
    __syncthreads();
    const int ng = __popc(s_wm[0]) + __popc(s_wm[1]) + __popc(s_wm[2]) + __popc(s_wm[3]);

    // ── Stage 2: per-point accumulation ──
    const int tz = tid & (TZ - 1);
    const int ty = (tid / TZ) % TY;
    const int tx = tid / (TZ * TY);
    const int x = bx*TX + tx;
    const int y = by*TY + ty;
    const int z = tz;
    const int n = (x * NY + y) * NZ + z;

    // Analytic grid coords; separate mul/add rounding to match jnp exactly
    const float px = __fadd_rn(__fmul_rn((float)x + 0.5f, 0.8f), -40.0f);
    const float py = __fadd_rn(__fmul_rn((float)y + 0.5f, 0.8f), -40.0f);
    const float pz = __fadd_rn(__fmul_rn((float)z + 0.5f, 0.8f), -1.0f);

    float sum_d = 0.0f, cnt = 0.0f;
    float sf[F];
    #pragma unroll
    for (int j = 0; j < F; j++) sf[j] = 0.0f;

    for (int k = 0; k < ng; k++) {
        float dx = px - s_mu[k][0];
        float dy = py - s_mu[k][1];
        float dz = pz - s_mu[k][2];
        if (fabsf(dx) > s_hw[k][0] || fabsf(dy) > s_hw[k][1] || fabsf(dz) > s_hw[k][2])
            continue;

        float maha = s_ic[k][0]*dx*dx + s_ic[k][3]*dy*dy + s_ic[k][5]*dz*dz
                   + 2.0f * (s_ic[k][1]*dx*dy + s_ic[k][2]*dx*dz + s_ic[k][4]*dy*dz);
        if (maha <= 4.0f) {
            float w = __expf(-0.5f * maha);
            cnt += 1.0f;
            sum_d += s_opac[k] * w;
            #pragma unroll
            for (int j = 0; j < F; j++) sf[j] += s_of[k][j] * w;
        }
    }

    const float invc = (cnt > 0.0f) ? (1.0f / cnt) : 0.0f;
    out[n] = sum_d * invc;

    float4* fo = reinterpret_cast<float4*>(out + NPTS + (size_t)n * F);
    #pragma unroll
    for (int j = 0; j < F/4; j++) {
        float4 v;
        v.x = sf[j*4 + 0] * invc;
        v.y = sf[j*4 + 1] * invc;
        v.z = sf[j*4 + 2] * invc;
        v.w = sf[j*4 + 3] * invc;
        fo[j] = v;
    }
}

extern "C" void kernel_launch(void* const* d_in, const int* in_sizes, int n_in,
                              void* d_out, int out_size) {
    // d_in[0] = grid_coords (unused; recomputed analytically)
    const float* means  = (const float*)d_in[1];  // (1, 128, 3)
    const float* opac   = (const float*)d_in[2];  // (1, 128, 1)
    const float* feats  = (const float*)d_in[3];  // (1, 128, 16)
    const float* covs   = (const float*)d_in[4];  // (1, 128, 3, 3)
    float* out = (float*)d_out;                   // [dens 80000 | feats 80000*16]

    dim3 gridDim(NX / TX, NY / TY);   // (25, 10) = 250 blocks
    fused_splat_kernel<<<gridDim, TPB>>>(means, opac, feats, covs, out);
}

// round 5
// speedup vs baseline: 1.4052x; 1.4052x over previous
#include <cuda_runtime.h>

#define G   128
#define F   16
#define NX  100
#define NY  100
#define NZ  8
#define NPTS (NX*NY*NZ)

#define TX  4
#define TY  10
#define TZH 4                 // threads along z; each handles 2 adjacent voxels
#define TPB (TX*TY*TZH)       // 160

__global__ __launch_bounds__(TPB)
void fused_splat_kernel(const float* __restrict__ means,
                        const float* __restrict__ opac,
                        const float* __restrict__ feats,
                        const float* __restrict__ covs,
                        float* __restrict__ out) {
    __shared__ float4 s_a[G];        // mx, my, mz, opac
    __shared__ float4 s_b[G];        // hwx, hwy, hwz, i00
    __shared__ float4 s_c[G];        // i01, i02, i11, i12
    __shared__ float  s_i22[G];
    __shared__ float4 s_of[G][F/4];  // opac * features
    __shared__ unsigned s_wm[4];

    const int tid = threadIdx.x;
    const int bx  = blockIdx.x;      // 0..24
    const int by  = blockIdx.y;      // 0..9

    const float x0 = (bx*TX + 0.5f) * 0.8f - 40.0f;
    const float x1 = (bx*TX + TX - 0.5f) * 0.8f - 40.0f;
    const float y0 = (by*TY + 0.5f) * 0.8f - 40.0f;
    const float y1 = (by*TY + TY - 0.5f) * 0.8f - 40.0f;
    const float z0 = 0.5f * 0.8f - 1.0f;
    const float z1 = (NZ - 0.5f) * 0.8f - 1.0f;

    // ── Stage 1a: hoisted loads + per-axis ellipsoid-AABB cull (warps 0..3) ──
    bool keep = false;
    float mx, my, mz, hwx, hwy, hwz;
    float c0, c1, c2, c3, c4, c5, c6, c7, c8;
    if (tid < G) {
        const float* Cp = covs + tid*9;
        c0 = Cp[0]; c1 = Cp[1]; c2 = Cp[2];
        c3 = Cp[3]; c4 = Cp[4]; c5 = Cp[5];
        c6 = Cp[6]; c7 = Cp[7]; c8 = Cp[8];
        mx = means[tid*3 + 0];
        my = means[tid*3 + 1];
        mz = means[tid*3 + 2];
        hwx = 2.0f * sqrtf(c0) * 1.0002f + 1e-3f;
        hwy = 2.0f * sqrtf(c4) * 1.0002f + 1e-3f;
        hwz = 2.0f * sqrtf(c8) * 1.0002f + 1e-3f;
        const float dxm = fabsf(fminf(fmaxf(mx, x0), x1) - mx);
        const float dym = fabsf(fminf(fmaxf(my, y0), y1) - my);
        const float dzm = fabsf(fminf(fmaxf(mz, z0), z1) - mz);
        keep = (dxm <= hwx) && (dym <= hwy) && (dzm <= hwz);
        const unsigned m = __ballot_sync(0xffffffffu, keep);
        if ((tid & 31) == 0) s_wm[tid >> 5] = m;
    }
    __syncthreads();

    // ── Stage 1b: deterministic compaction + per-survivor prep (regs only, no reload) ──
    if (keep) {
        const int w = tid >> 5, lane = tid & 31;
        int k = __popc(s_wm[w] & ((1u << lane) - 1u));
        #pragma unroll
        for (int i = 0; i < 4; i++) if (i < w) k += __popc(s_wm[i]);

        double m00 = c0, m01 = c1, m02 = c2;
        double m10 = c3, m11 = c4, m12 = c5;
        double m20 = c6, m21 = c7, m22 = c8;
        double A00 = m11*m22 - m12*m21;
        double A01 = m02*m21 - m01*m22;
        double A02 = m01*m12 - m02*m11;
        double A10 = m12*m20 - m10*m22;
        double A11 = m00*m22 - m02*m20;
        double A12 = m02*m10 - m00*m12;
        double A20 = m10*m21 - m11*m20;
        double A21 = m01*m20 - m00*m21;
        double A22 = m00*m11 - m01*m10;
        double det = m00*A00 + m01*A10 + m02*A20;

        // Newton reciprocal (fp32 seed + 2 double iterations) — avoids DDIV CALL
        double r = (double)__fdividef(1.0f, (float)det);
        r = fma(r, fma(-det, r, 1.0), r);
        r = fma(r, fma(-det, r, 1.0), r);

        const float i00 = (float)(A00 * r);
        const float i01 = (float)(0.5 * (A01 + A10) * r);
        const float i02 = (float)(0.5 * (A02 + A20) * r);
        const float i11 = (float)(A11 * r);
        const float i12 = (float)(0.5 * (A12 + A21) * r);
        const float i22 = (float)(A22 * r);

        const float o = opac[tid];
        s_a[k] = make_float4(mx, my, mz, o);
        s_b[k] = make_float4(hwx, hwy, hwz, i00);
        s_c[k] = make_float4(i01, i02, i11, i12);
        s_i22[k] = i22;
        const float4* fr = reinterpret_cast<const float4*>(feats + tid*F);
        #pragma unroll
        for (int j = 0; j < F/4; j++) {
            float4 v = fr[j];
            s_of[k][j] = make_float4(o*v.x, o*v.y, o*v.z, o*v.w);
        }
    }
    __syncthreads();
    const int ng = __popc(s_wm[0]) + __popc(s_wm[1]) + __popc(s_wm[2]) + __popc(s_wm[3]);

    // ── Stage 2: two adjacent z-voxels per thread ──
    const int tzh = tid & (TZH - 1);
    const int ty  = (tid / TZH) % TY;
    const int tx  = tid / (TZH * TY);
    const int x   = bx*TX + tx;
    const int y   = by*TY + ty;
    const int za  = tzh * 2;
    const int n0  = (x * NY + y) * NZ + za;   // even; n1 = n0+1

    const float px  = __fadd_rn(__fmul_rn((float)x + 0.5f, 0.8f), -40.0f);
    const float py  = __fadd_rn(__fmul_rn((float)y + 0.5f, 0.8f), -40.0f);
    const float pz0 = __fadd_rn(__fmul_rn((float)za + 0.5f, 0.8f), -1.0f);
    const float pz1 = __fadd_rn(__fmul_rn((float)za + 1.5f, 0.8f), -1.0f);

    float sd0 = 0.0f, sd1 = 0.0f, cnt0 = 0.0f, cnt1 = 0.0f;
    float sf0[F], sf1[F];
    #pragma unroll
    for (int j = 0; j < F; j++) { sf0[j] = 0.0f; sf1[j] = 0.0f; }

    for (int k = 0; k < ng; k++) {
        const float4 a = s_a[k];
        const float4 b = s_b[k];
        const float dx = px - a.x;
        const float dy = py - a.y;
        if (fabsf(dx) > b.x || fabsf(dy) > b.y) continue;
        const float dz0 = pz0 - a.z;
        const float dz1 = pz1 - a.z;
        const bool in0 = fabsf(dz0) <= b.z;
        const bool in1 = fabsf(dz1) <= b.z;
        if (!in0 && !in1) continue;

        const float4 c = s_c[k];
        const float i22 = s_i22[k];
        // shared xy part + shared cross coefficient
        const float qxy = b.w*dx*dx + c.z*dy*dy + 2.0f*c.x*dx*dy;
        const float cz  = 2.0f * (c.y*dx + c.w*dy);

        float w0 = 0.0f, w1 = 0.0f;
        bool h0 = false, h1 = false;
        if (in0) {
            const float maha = qxy + cz*dz0 + i22*dz0*dz0;
            if (maha <= 4.0f) { w0 = __expf(-0.5f*maha); h0 = true; }
        }
        if (in1) {
            const float maha = qxy + cz*dz1 + i22*dz1*dz1;
            if (maha <= 4.0f) { w1 = __expf(-0.5f*maha); h1 = true; }
        }
        if (!h0 && !h1) continue;

        if (h0) { cnt0 += 1.0f; sd0 += a.w * w0; }
        if (h1) { cnt1 += 1.0f; sd1 += a.w * w1; }
        #pragma unroll
        for (int j = 0; j < F/4; j++) {
            const float4 of = s_of[k][j];
            if (h0) {
                sf0[j*4+0] += of.x * w0; sf0[j*4+1] += of.y * w0;
                sf0[j*4+2] += of.z * w0; sf0[j*4+3] += of.w * w0;
            }
            if (h1) {
                sf1[j*4+0] += of.x * w1; sf1[j*4+1] += of.y * w1;
                sf1[j*4+2] += of.z * w1; sf1[j*4+3] += of.w * w1;
            }
        }
    }

    const float ic0 = (cnt0 > 0.0f) ? (1.0f / cnt0) : 0.0f;
    const float ic1 = (cnt1 > 0.0f) ? (1.0f / cnt1) : 0.0f;

    float2 dpair;
    dpair.x = sd0 * ic0;
    dpair.y = sd1 * ic1;
    *reinterpret_cast<float2*>(out + n0) = dpair;

    float4* fo = reinterpret_cast<float4*>(out + NPTS + (size_t)n0 * F);
    #pragma unroll
    for (int j = 0; j < F/4; j++) {
        float4 v;
        v.x = sf0[j*4+0] * ic0; v.y = sf0[j*4+1] * ic0;
        v.z = sf0[j*4+2] * ic0; v.w = sf0[j*4+3] * ic0;
        fo[j] = v;
    }
    #pragma unroll
    for (int j = 0; j < F/4; j++) {
        float4 v;
        v.x = sf1[j*4+0] * ic1; v.y = sf1[j*4+1] * ic1;
        v.z = sf1[j*4+2] * ic1; v.w = sf1[j*4+3] * ic1;
        fo[F/4 + j] = v;
    }
}

extern "C" void kernel_launch(void* const* d_in, const int* in_sizes, int n_in,
                              void* d_out, int out_size) {
    // d_in[0] = grid_coords (unused; recomputed analytically)
    const float* means  = (const float*)d_in[1];  // (1, 128, 3)
    const float* opac   = (const float*)d_in[2];  // (1, 128, 1)
    const float* feats  = (const float*)d_in[3];  // (1, 128, 16)
    const float* covs   = (const float*)d_in[4];  // (1, 128, 3, 3)
    float* out = (float*)d_out;                   // [dens 80000 | feats 80000*16]

    dim3 gridDim(NX / TX, NY / TY);   // (25, 10) = 250 blocks, 160 thr each
    fused_splat_kernel<<<gridDim, TPB>>>(means, opac, feats, covs, out);
}

// round 8
// speedup vs baseline: 1.4345x; 1.0208x over previous
#include <cuda_runtime.h>

#define G     128
#define F     16
#define NX    100
#define NY    100
#define NZ    8
#define NPTS  (NX*NY*NZ)

#define TX    4
#define TY    10
#define TZH   4                // point-slots along z (2 voxels each)
#define SLOTS (TX*TY*TZH)      // 160
#define TPB   (SLOTS*2)        // 320: two Gaussian-halves per point-slot

__global__ __launch_bounds__(TPB)
void fused_splat_kernel(const float* __restrict__ means,
                        const float* __restrict__ opac,
                        const float* __restrict__ feats,
                        const float* __restrict__ covs,
                        float* __restrict__ out) {
    __shared__ float4 s_a[G];        // mx, my, mz, opac
    __shared__ float4 s_b[G];        // hwx, hwy, hwz, i00
    __shared__ float4 s_c[G];        // i01, i02, i11, i12
    __shared__ float  s_i22[G];
    __shared__ float4 s_of[G][F/4];  // opac * features
    __shared__ unsigned s_wm[4];
    // group-1 partials, transposed for conflict-free access
    __shared__ float s_pdc[4][SLOTS];      // sd0, sd1, cnt0, cnt1
    __shared__ float s_pf[2*F][SLOTS];     // feats partials (vox0 then vox1)

    const int tid = threadIdx.x;
    const int bx  = blockIdx.x;      // 0..24
    const int by  = blockIdx.y;      // 0..9

    const float x0 = (bx*TX + 0.5f) * 0.8f - 40.0f;
    const float x1 = (bx*TX + TX - 0.5f) * 0.8f - 40.0f;
    const float y0 = (by*TY + 0.5f) * 0.8f - 40.0f;
    const float y1 = (by*TY + TY - 0.5f) * 0.8f - 40.0f;
    const float z0 = 0.5f * 0.8f - 1.0f;
    const float z1 = (NZ - 0.5f) * 0.8f - 1.0f;

    // ── Stage 1a: hoisted loads + per-axis ellipsoid-AABB cull (warps 0..3) ──
    bool keep = false;
    float mx, my, mz, hwx, hwy, hwz;
    float c0, c1, c2, c3, c4, c5, c6, c7, c8;
    if (tid < G) {
        const float* Cp = covs + tid*9;
        c0 = Cp[0]; c1 = Cp[1]; c2 = Cp[2];
        c3 = Cp[3]; c4 = Cp[4]; c5 = Cp[5];
        c6 = Cp[6]; c7 = Cp[7]; c8 = Cp[8];
        mx = means[tid*3 + 0];
        my = means[tid*3 + 1];
        mz = means[tid*3 + 2];
        hwx = 2.0f * sqrtf(c0) * 1.0002f + 1e-3f;
        hwy = 2.0f * sqrtf(c4) * 1.0002f + 1e-3f;
        hwz = 2.0f * sqrtf(c8) * 1.0002f + 1e-3f;
        const float dxm = fabsf(fminf(fmaxf(mx, x0), x1) - mx);
        const float dym = fabsf(fminf(fmaxf(my, y0), y1) - my);
        const float dzm = fabsf(fminf(fmaxf(mz, z0), z1) - mz);
        keep = (dxm <= hwx) && (dym <= hwy) && (dzm <= hwz);
        const unsigned m = __ballot_sync(0xffffffffu, keep);
        if ((tid & 31) == 0) s_wm[tid >> 5] = m;
    }
    __syncthreads();

    // ── Stage 1b: deterministic compaction + per-survivor prep ──
    if (keep) {
        const int w = tid >> 5, lane = tid & 31;
        int k = __popc(s_wm[w] & ((1u << lane) - 1u));
        #pragma unroll
        for (int i = 0; i < 4; i++) if (i < w) k += __popc(s_wm[i]);

        double m00 = c0, m01 = c1, m02 = c2;
        double m10 = c3, m11 = c4, m12 = c5;
        double m20 = c6, m21 = c7, m22 = c8;
        double A00 = m11*m22 - m12*m21;
        double A01 = m02*m21 - m01*m22;
        double A02 = m01*m12 - m02*m11;
        double A10 = m12*m20 - m10*m22;
        double A11 = m00*m22 - m02*m20;
        double A12 = m02*m10 - m00*m12;
        double A20 = m10*m21 - m11*m20;
        double A21 = m01*m20 - m00*m21;
        double A22 = m00*m11 - m01*m10;
        double det = m00*A00 + m01*A10 + m02*A20;

        // Newton reciprocal (fp32 seed + 2 double iterations) — no DDIV CALL
        double r = (double)__fdividef(1.0f, (float)det);
        r = fma(r, fma(-det, r, 1.0), r);
        r = fma(r, fma(-det, r, 1.0), r);

        const float i00 = (float)(A00 * r);
        const float i01 = (float)(0.5 * (A01 + A10) * r);
        const float i02 = (float)(0.5 * (A02 + A20) * r);
        const float i11 = (float)(A11 * r);
        const float i12 = (float)(0.5 * (A12 + A21) * r);
        const float i22 = (float)(A22 * r);

        const float o = opac[tid];
        s_a[k] = make_float4(mx, my, mz, o);
        s_b[k] = make_float4(hwx, hwy, hwz, i00);
        s_c[k] = make_float4(i01, i02, i11, i12);
        s_i22[k] = i22;
        const float4* fr = reinterpret_cast<const float4*>(feats + tid*F);
        #pragma unroll
        for (int j = 0; j < F/4; j++) {
            float4 v = fr[j];
            s_of[k][j] = make_float4(o*v.x, o*v.y, o*v.z, o*v.w);
        }
    }
    __syncthreads();
    const int ng = __popc(s_wm[0]) + __popc(s_wm[1]) + __popc(s_wm[2]) + __popc(s_wm[3]);

    // ── Stage 2: 160 point-slots × 2 Gaussian-halves ──
    const int gh = (tid >= SLOTS) ? 1 : 0;   // warps 0-4: gh0, warps 5-9: gh1
    const int s  = tid - gh * SLOTS;

    const int tzh = s & (TZH - 1);
    const int ty  = (s / TZH) % TY;
    const int tx  = s / (TZH * TY);
    const int x   = bx*TX + tx;
    const int y   = by*TY + ty;
    const int za  = tzh * 2;
    const int n0  = (x * NY + y) * NZ + za;

    const float px  = __fadd_rn(__fmul_rn((float)x + 0.5f, 0.8f), -40.0f);
    const float py  = __fadd_rn(__fmul_rn((float)y + 0.5f, 0.8f), -40.0f);
    const float pz0 = __fadd_rn(__fmul_rn((float)za + 0.5f, 0.8f), -1.0f);
    const float pz1 = __fadd_rn(__fmul_rn((float)za + 1.5f, 0.8f), -1.0f);

    float sd0 = 0.0f, sd1 = 0.0f, cnt0 = 0.0f, cnt1 = 0.0f;
    float sf0[F], sf1[F];
    #pragma unroll
    for (int j = 0; j < F; j++) { sf0[j] = 0.0f; sf1[j] = 0.0f; }

    for (int k = gh; k < ng; k += 2) {
        const float4 a = s_a[k];
        const float4 b = s_b[k];
        const float dx = px - a.x;
        const float dy = py - a.y;
        if (fabsf(dx) > b.x || fabsf(dy) > b.y) continue;
        const float dz0 = pz0 - a.z;
        const float dz1 = pz1 - a.z;
        const bool in0 = fabsf(dz0) <= b.z;
        const bool in1 = fabsf(dz1) <= b.z;
        if (!in0 && !in1) continue;

        const float4 c = s_c[k];
        const float i22 = s_i22[k];
        const float qxy = b.w*dx*dx + c.z*dy*dy + 2.0f*c.x*dx*dy;
        const float cz  = 2.0f * (c.y*dx + c.w*dy);

        float w0 = 0.0f, w1 = 0.0f;
        bool h0 = false, h1 = false;
        if (in0) {
            const float maha = qxy + cz*dz0 + i22*dz0*dz0;
            if (maha <= 4.0f) { w0 = __expf(-0.5f*maha); h0 = true; }
        }
        if (in1) {
            const float maha = qxy + cz*dz1 + i22*dz1*dz1;
            if (maha <= 4.0f) { w1 = __expf(-0.5f*maha); h1 = true; }
        }
        if (!h0 && !h1) continue;

        if (h0) { cnt0 += 1.0f; sd0 += a.w * w0; }
        if (h1) { cnt1 += 1.0f; sd1 += a.w * w1; }
        #pragma unroll
        for (int j = 0; j < F/4; j++) {
            const float4 of = s_of[k][j];
            if (h0) {
                sf0[j*4+0] += of.x * w0; sf0[j*4+1] += of.y * w0;
                sf0[j*4+2] += of.z * w0; sf0[j*4+3] += of.w * w0;
            }
            if (h1) {
                sf1[j*4+0] += of.x * w1; sf1[j*4+1] += of.y * w1;
                sf1[j*4+2] += of.z * w1; sf1[j*4+3] += of.w * w1;
            }
        }
    }

    // ── Merge: group 1 publishes partials; group 0 adds (fixed order) + writes ──
    if (gh == 1) {
        s_pdc[0][s] = sd0; s_pdc[1][s] = sd1;
        s_pdc[2][s] = cnt0; s_pdc[3][s] = cnt1;
        #pragma unroll
        for (int j = 0; j < F; j++) { s_pf[j][s] = sf0[j]; s_pf[F + j][s] = sf1[j]; }
    }
    __syncthreads();
    if (gh == 0) {
        sd0  += s_pdc[0][s]; sd1  += s_pdc[1][s];
        cnt0 += s_pdc[2][s]; cnt1 += s_pdc[3][s];
        #pragma unroll
        for (int j = 0; j < F; j++) { sf0[j] += s_pf[j][s]; sf1[j] += s_pf[F + j][s]; }

        const float ic0 = (cnt0 > 0.0f) ? (1.0f / cnt0) : 0.0f;
        const float ic1 = (cnt1 > 0.0f) ? (1.0f / cnt1) : 0.0f;

        float2 dpair;
        dpair.x = sd0 * ic0;
        dpair.y = sd1 * ic1;
        *reinterpret_cast<float2*>(out + n0) = dpair;

        float4* fo = reinterpret_cast<float4*>(out + NPTS + (size_t)n0 * F);
        #pragma unroll
        for (int j = 0; j < F/4; j++) {
            float4 v;
            v.x = sf0[j*4+0] * ic0; v.y = sf0[j*4+1] * ic0;
            v.z = sf0[j*4+2] * ic0; v.w = sf0[j*4+3] * ic0;
            fo[j] = v;
        }
        #pragma unroll
        for (int j = 0; j < F/4; j++) {
            float4 v;
            v.x = sf1[j*4+0] * ic1; v.y = sf1[j*4+1] * ic1;
            v.z = sf1[j*4+2] * ic1; v.w = sf1[j*4+3] * ic1;
            fo[F/4 + j] = v;
        }
    }
}

extern "C" void kernel_launch(void* const* d_in, const int* in_sizes, int n_in,
                              void* d_out, int out_size) {
    // d_in[0] = grid_coords (unused; recomputed analytically)
    const float* means  = (const float*)d_in[1];  // (1, 128, 3)
    const float* opac   = (const float*)d_in[2];  // (1, 128, 1)
    const float* feats  = (const float*)d_in[3];  // (1, 128, 16)
    const float* covs   = (const float*)d_in[4];  // (1, 128, 3, 3)
    float* out = (float*)d_out;                   // [dens 80000 | feats 80000*16]

    dim3 gridDim(NX / TX, NY / TY);   // (25, 10) = 250 blocks, 320 thr each
    fused_splat_kernel<<<gridDim, TPB>>>(means, opac, feats, covs, out);
}

// round 13
// speedup vs baseline: 1.7214x; 1.2000x over previous
#include <cuda_runtime.h>

#define G     128
#define F     16
#define NX    100
#define NY    100
#define NZ    8
#define NPTS  (NX*NY*NZ)

#define TX    4
#define TY    5
#define TZ    8
#define TPB   (TX*TY*TZ)   // 160

__global__ __launch_bounds__(TPB)
void fused_splat_kernel(const float* __restrict__ means,
                        const float* __restrict__ opac,
                        const float* __restrict__ feats,
                        const float* __restrict__ covs,
                        float* __restrict__ out) {
    __shared__ float4 s_a[G];        // mx, my, mz, opac
    __shared__ float4 s_b[G];        // hwx, hwy, hwz, i00
    __shared__ float4 s_c[G];        // i01, i02, i11, i12
    __shared__ float  s_i22[G];
    __shared__ float4 s_of[G][F/4];  // opac * features
    __shared__ unsigned s_wm[4];

    const int tid = threadIdx.x;
    const int bx  = blockIdx.x;      // 0..24
    const int by  = blockIdx.y;      // 0..19

    const float x0 = (bx*TX + 0.5f) * 0.8f - 40.0f;
    const float x1 = (bx*TX + TX - 0.5f) * 0.8f - 40.0f;
    const float y0 = (by*TY + 0.5f) * 0.8f - 40.0f;
    const float y1 = (by*TY + TY - 0.5f) * 0.8f - 40.0f;
    const float z0 = 0.5f * 0.8f - 1.0f;
    const float z1 = (NZ - 0.5f) * 0.8f - 1.0f;

    // ── Stage 1a: cull on means + cov diagonal (threads 0..127 = 4 full warps) ──
    bool keep = false;
    float mx, my, mz, hwx, hwy, hwz;
    if (tid < G) {
        const float* Cp = covs + tid*9;
        const float cd0 = Cp[0], cd4 = Cp[4], cd8 = Cp[8];
        mx = means[tid*3 + 0];
        my = means[tid*3 + 1];
        mz = means[tid*3 + 2];
        hwx = 2.0f * sqrtf(cd0) * 1.0002f + 1e-3f;
        hwy = 2.0f * sqrtf(cd4) * 1.0002f + 1e-3f;
        hwz = 2.0f * sqrtf(cd8) * 1.0002f + 1e-3f;
        const float dxm = fabsf(fminf(fmaxf(mx, x0), x1) - mx);
        const float dym = fabsf(fminf(fmaxf(my, y0), y1) - my);
        const float dzm = fabsf(fminf(fmaxf(mz, z0), z1) - mz);
        keep = (dxm <= hwx) && (dym <= hwy) && (dzm <= hwz);
        const unsigned m = __ballot_sync(0xffffffffu, keep);
        if ((tid & 31) == 0) s_wm[tid >> 5] = m;
    }
    __syncthreads();

    // ── Stage 1b: compaction + fp32 inversion w/ one Newton refinement ──
    if (keep) {
        const int w = tid >> 5, lane = tid & 31;
        int k = __popc(s_wm[w] & ((1u << lane) - 1u));
        #pragma unroll
        for (int i = 0; i < 4; i++) if (i < w) k += __popc(s_wm[i]);

        const float* C = covs + tid*9;
        const float m00 = C[0], m01 = C[1], m02 = C[2];
        const float m10 = C[3], m11 = C[4], m12 = C[5];
        const float m20 = C[6], m21 = C[7], m22 = C[8];

        // fp32 adjugate
        const float A00 = m11*m22 - m12*m21;
        const float A01 = m02*m21 - m01*m22;
        const float A02 = m01*m12 - m02*m11;
        const float A10 = m12*m20 - m10*m22;
        const float A11 = m00*m22 - m02*m20;
        const float A12 = m02*m10 - m00*m12;
        const float A20 = m10*m21 - m11*m20;
        const float A21 = m01*m20 - m00*m21;
        const float A22 = m00*m11 - m01*m10;
        const float det = m00*A00 + m01*A10 + m02*A20;

        // fp32 Newton-refined reciprocal of det
        float r = __fdividef(1.0f, det);
        r = fmaf(r, fmaf(-det, r, 1.0f), r);

        // symmetric initial inverse X0
        float x00 = A00 * r;
        float x01 = 0.5f * (A01 + A10) * r;
        float x02 = 0.5f * (A02 + A20) * r;
        float x11 = A11 * r;
        float x12 = 0.5f * (A12 + A21) * r;
        float x22 = A22 * r;

        // One Newton step: X1 = 2*X0 - X0*(C*X0), symmetrized.
        // M = C * X0  (C symmetric rows: (m00,m01,m02),(m01,m11,m12),(m02,m12,m22))
        const float M00 = m00*x00 + m01*x01 + m02*x02;
        const float M01 = m00*x01 + m01*x11 + m02*x12;
        const float M02 = m00*x02 + m01*x12 + m02*x22;
        const float M10 = m10*x00 + m11*x01 + m12*x02;
        const float M11 = m10*x01 + m11*x11 + m12*x12;
        const float M12 = m10*x02 + m11*x12 + m12*x22;
        const float M20 = m20*x00 + m21*x01 + m22*x02;
        const float M21 = m20*x01 + m21*x11 + m22*x12;
        const float M22 = m20*x02 + m21*x12 + m22*x22;
        // T = X0 * M
        const float T00 = x00*M00 + x01*M10 + x02*M20;
        const float T01 = x00*M01 + x01*M11 + x02*M21;
        const float T02 = x00*M02 + x01*M12 + x02*M22;
        const float T10 = x01*M00 + x11*M10 + x12*M20;
        const float T11 = x01*M01 + x11*M11 + x12*M21;
        const float T12 = x01*M02 + x11*M12 + x12*M22;
        const float T20 = x02*M00 + x12*M10 + x22*M20;
        const float T21 = x02*M01 + x12*M11 + x22*M21;
        const float T22 = x02*M02 + x12*M12 + x22*M22;

        const float i00 = 2.0f*x00 - T00;
        const float i01 = 2.0f*x01 - 0.5f*(T01 + T10);
        const float i02 = 2.0f*x02 - 0.5f*(T02 + T20);
        const float i11 = 2.0f*x11 - T11;
        const float i12 = 2.0f*x12 - 0.5f*(T12 + T21);
        const float i22 = 2.0f*x22 - T22;

        const float o = opac[tid];
        s_a[k] = make_float4(mx, my, mz, o);
        s_b[k] = make_float4(hwx, hwy, hwz, i00);
        s_c[k] = make_float4(i01, i02, i11, i12);
        s_i22[k] = i22;
        const float4* fr = reinterpret_cast<const float4*>(feats + tid*F);
        #pragma unroll
        for (int j = 0; j < F/4; j++) {
            float4 v = fr[j];
            s_of[k][j] = make_float4(o*v.x, o*v.y, o*v.z, o*v.w);
        }
    }
    __syncthreads();
    const int ng = __popc(s_wm[0]) + __popc(s_wm[1]) + __popc(s_wm[2]) + __popc(s_wm[3]);

    // ── Stage 2: one voxel per thread ──
    const int tz = tid & (TZ - 1);
    const int ty = (tid / TZ) % TY;
    const int tx = tid / (TZ * TY);
    const int x = bx*TX + tx;
    const int y = by*TY + ty;
    const int z = tz;
    const int n = (x * NY + y) * NZ + z;

    const float px = __fadd_rn(__fmul_rn((float)x + 0.5f, 0.8f), -40.0f);
    const float py = __fadd_rn(__fmul_rn((float)y + 0.5f, 0.8f), -40.0f);
    const float pz = __fadd_rn(__fmul_rn((float)z + 0.5f, 0.8f), -1.0f);

    float sum_d = 0.0f, cnt = 0.0f;
    float sf[F];
    #pragma unroll
    for (int j = 0; j < F; j++) sf[j] = 0.0f;

    for (int k = 0; k < ng; k++) {
        const float4 a = s_a[k];
        const float4 b = s_b[k];
        const float dx = px - a.x;
        const float dy = py - a.y;
        const float dz = pz - a.z;
        if (fabsf(dx) > b.x || fabsf(dy) > b.y || fabsf(dz) > b.z) continue;

        const float4 c = s_c[k];
        const float i22 = s_i22[k];
        const float maha = b.w*dx*dx + c.z*dy*dy + i22*dz*dz
                         + 2.0f * (c.x*dx*dy + c.y*dx*dz + c.w*dy*dz);
        if (maha <= 4.0f) {
            const float wgt = __expf(-0.5f * maha);
            cnt += 1.0f;
            sum_d += a.w * wgt;
            #pragma unroll
            for (int j = 0; j < F/4; j++) {
                const float4 of = s_of[k][j];
                sf[j*4+0] += of.x * wgt; sf[j*4+1] += of.y * wgt;
                sf[j*4+2] += of.z * wgt; sf[j*4+3] += of.w * wgt;
            }
        }
    }

    const float invc = (cnt > 0.0f) ? (1.0f / cnt) : 0.0f;
    out[n] = sum_d * invc;

    float4* fo = reinterpret_cast<float4*>(out + NPTS + (size_t)n * F);
    #pragma unroll
    for (int j = 0; j < F/4; j++) {
        float4 v;
        v.x = sf[j*4+0] * invc; v.y = sf[j*4+1] * invc;
        v.z = sf[j*4+2] * invc; v.w = sf[j*4+3] * invc;
        fo[j] = v;
    }
}

extern "C" void kernel_launch(void* const* d_in, const int* in_sizes, int n_in,
                              void* d_out, int out_size) {
    // d_in[0] = grid_coords (unused; recomputed analytically)
    const float* means  = (const float*)d_in[1];  // (1, 128, 3)
    const float* opac   = (const float*)d_in[2];  // (1, 128, 1)
    const float* feats  = (const float*)d_in[3];  // (1, 128, 16)
    const float* covs   = (const float*)d_in[4];  // (1, 128, 3, 3)
    float* out = (float*)d_out;                   // [dens 80000 | feats 80000*16]

    dim3 gridDim(NX / TX, NY / TY);   // (25, 20) = 500 blocks, 160 thr each
    fused_splat_kernel<<<gridDim, TPB>>>(means, opac, feats, covs, out);
}

// round 14
// speedup vs baseline: 1.7276x; 1.0036x over previous
#include <cuda_runtime.h>

#define G     128
#define F     16
#define NX    100
#define NY    100
#define NZ    8
#define NPTS  (NX*NY*NZ)

#define TX    4
#define TY    5
#define TZ    8
#define TPB   (TX*TY*TZ)   // 160

__global__ __launch_bounds__(TPB)
void fused_splat_kernel(const float* __restrict__ means,
                        const float* __restrict__ opac,
                        const float* __restrict__ feats,
                        const float* __restrict__ covs,
                        float* __restrict__ out) {
    // Segmented survivor storage: warp w owns slots [w*32, w*32+32)
    __shared__ float4 s_a[G];        // mx, my, mz, opac
    __shared__ float4 s_b[G];        // hwx, hwy, hwz, i00
    __shared__ float4 s_c[G];        // i01, i02, i11, i12
    __shared__ float  s_i22[G];
    __shared__ float4 s_of[G][F/4];  // opac * features
    __shared__ int    s_cnt[4];      // survivors per warp segment

    const int tid = threadIdx.x;
    const int bx  = blockIdx.x;      // 0..24
    const int by  = blockIdx.y;      // 0..19

    const float x0 = (bx*TX + 0.5f) * 0.8f - 40.0f;
    const float x1 = (bx*TX + TX - 0.5f) * 0.8f - 40.0f;
    const float y0 = (by*TY + 0.5f) * 0.8f - 40.0f;
    const float y1 = (by*TY + TY - 0.5f) * 0.8f - 40.0f;
    const float z0 = 0.5f * 0.8f - 1.0f;
    const float z1 = (NZ - 0.5f) * 0.8f - 1.0f;

    // ── Stage 1: one hoisted load batch, cull, single-barrier segmented compaction ──
    if (tid < G) {
        // All loads issued up front (independent → one latency round)
        const float* Cp = covs + tid*9;
        const float m00 = Cp[0], m01 = Cp[1], m02 = Cp[2];
        const float m10 = Cp[3], m11 = Cp[4], m12 = Cp[5];
        const float m20 = Cp[6], m21 = Cp[7], m22 = Cp[8];
        const float mx = means[tid*3 + 0];
        const float my = means[tid*3 + 1];
        const float mz = means[tid*3 + 2];
        const float o  = opac[tid];
        const float4* fr = reinterpret_cast<const float4*>(feats + tid*F);
        const float4 f0 = fr[0], f1 = fr[1], f2 = fr[2], f3 = fr[3];

        const float hwx = 2.0f * sqrtf(m00) * 1.0002f + 1e-3f;
        const float hwy = 2.0f * sqrtf(m11) * 1.0002f + 1e-3f;
        const float hwz = 2.0f * sqrtf(m22) * 1.0002f + 1e-3f;
        const float dxm = fabsf(fminf(fmaxf(mx, x0), x1) - mx);
        const float dym = fabsf(fminf(fmaxf(my, y0), y1) - my);
        const float dzm = fabsf(fminf(fmaxf(mz, z0), z1) - mz);
        const bool keep = (dxm <= hwx) && (dym <= hwy) && (dzm <= hwz);

        const int w = tid >> 5, lane = tid & 31;
        const unsigned m = __ballot_sync(0xffffffffu, keep);
        if (lane == 0) s_cnt[w] = __popc(m);

        if (keep) {
            const int k = w*32 + __popc(m & ((1u << lane) - 1u));

            // fp32 adjugate + Newton-refined reciprocal det
            const float A00 = m11*m22 - m12*m21;
            const float A01 = m02*m21 - m01*m22;
            const float A02 = m01*m12 - m02*m11;
            const float A10 = m12*m20 - m10*m22;
            const float A11 = m00*m22 - m02*m20;
            const float A12 = m02*m10 - m00*m12;
            const float A20 = m10*m21 - m11*m20;
            const float A21 = m01*m20 - m00*m21;
            const float A22 = m00*m11 - m01*m10;
            const float det = m00*A00 + m01*A10 + m02*A20;
            float r = __fdividef(1.0f, det);
            r = fmaf(r, fmaf(-det, r, 1.0f), r);

            // symmetric X0
            const float x00 = A00 * r;
            const float x01 = 0.5f * (A01 + A10) * r;
            const float x02 = 0.5f * (A02 + A20) * r;
            const float x11 = A11 * r;
            const float x12 = 0.5f * (A12 + A21) * r;
            const float x22 = A22 * r;

            // One Newton step: X1 = 2*X0 - X0*(C*X0), symmetrized
            const float M00 = m00*x00 + m01*x01 + m02*x02;
            const float M01 = m00*x01 + m01*x11 + m02*x12;
            const float M02 = m00*x02 + m01*x12 + m02*x22;
            const float M10 = m10*x00 + m11*x01 + m12*x02;
            const float M11 = m10*x01 + m11*x11 + m12*x12;
            const float M12 = m10*x02 + m11*x12 + m12*x22;
            const float M20 = m20*x00 + m21*x01 + m22*x02;
            const float M21 = m20*x01 + m21*x11 + m22*x12;
            const float M22 = m20*x02 + m21*x12 + m22*x22;
            const float T00 = x00*M00 + x01*M10 + x02*M20;
            const float T01 = x00*M01 + x01*M11 + x02*M21;
            const float T02 = x00*M02 + x01*M12 + x02*M22;
            const float T10 = x01*M00 + x11*M10 + x12*M20;
            const float T11 = x01*M01 + x11*M11 + x12*M21;
            const float T12 = x01*M02 + x11*M12 + x12*M22;
            const float T20 = x02*M00 + x12*M10 + x22*M20;
            const float T21 = x02*M01 + x12*M11 + x22*M21;
            const float T22 = x02*M02 + x12*M12 + x22*M22;

            const float i00 = 2.0f*x00 - T00;
            const float i01 = 2.0f*x01 - 0.5f*(T01 + T10);
            const float i02 = 2.0f*x02 - 0.5f*(T02 + T20);
            const float i11 = 2.0f*x11 - T11;
            const float i12 = 2.0f*x12 - 0.5f*(T12 + T21);
            const float i22 = 2.0f*x22 - T22;

            s_a[k] = make_float4(mx, my, mz, o);
            s_b[k] = make_float4(hwx, hwy, hwz, i00);
            s_c[k] = make_float4(i01, i02, i11, i12);
            s_i22[k] = i22;
            s_of[k][0] = make_float4(o*f0.x, o*f0.y, o*f0.z, o*f0.w);
            s_of[k][1] = make_float4(o*f1.x, o*f1.y, o*f1.z, o*f1.w);
            s_of[k][2] = make_float4(o*f2.x, o*f2.y, o*f2.z, o*f2.w);
            s_of[k][3] = make_float4(o*f3.x, o*f3.y, o*f3.z, o*f3.w);
        }
    }
    __syncthreads();   // the only barrier

    // ── Stage 2: one voxel per thread, iterate 4 warp segments (fixed order) ──
    const int tz = tid & (TZ - 1);
    const int ty = (tid / TZ) % TY;
    const int tx = tid / (TZ * TY);
    const int x = bx*TX + tx;
    const int y = by*TY + ty;
    const int z = tz;
    const int n = (x * NY + y) * NZ + z;

    const float px = __fadd_rn(__fmul_rn((float)x + 0.5f, 0.8f), -40.0f);
    const float py = __fadd_rn(__fmul_rn((float)y + 0.5f, 0.8f), -40.0f);
    const float pz = __fadd_rn(__fmul_rn((float)z + 0.5f, 0.8f), -1.0f);

    float sum_d = 0.0f, cnt = 0.0f;
    float sf[F];
    #pragma unroll
    for (int j = 0; j < F; j++) sf[j] = 0.0f;

    #pragma unroll
    for (int w = 0; w < 4; w++) {
        const int e = s_cnt[w];
        for (int j = 0; j < e; j++) {
            const int k = w*32 + j;
            const float4 a = s_a[k];
            const float4 b = s_b[k];
            const float dx = px - a.x;
            const float dy = py - a.y;
            const float dz = pz - a.z;
            if (fabsf(dx) > b.x || fabsf(dy) > b.y || fabsf(dz) > b.z) continue;

            const float4 c = s_c[k];
            const float i22 = s_i22[k];
            const float maha = b.w*dx*dx + c.z*dy*dy + i22*dz*dz
                             + 2.0f * (c.x*dx*dy + c.y*dx*dz + c.w*dy*dz);
            if (maha <= 4.0f) {
                const float wgt = __expf(-0.5f * maha);
                cnt += 1.0f;
                sum_d += a.w * wgt;
                #pragma unroll
                for (int q = 0; q < F/4; q++) {
                    const float4 of = s_of[k][q];
                    sf[q*4+0] += of.x * wgt; sf[q*4+1] += of.y * wgt;
                    sf[q*4+2] += of.z * wgt; sf[q*4+3] += of.w * wgt;
                }
            }
        }
    }

    const float invc = (cnt > 0.0f) ? (1.0f / cnt) : 0.0f;
    out[n] = sum_d * invc;

    float4* fo = reinterpret_cast<float4*>(out + NPTS + (size_t)n * F);
    #pragma unroll
    for (int j = 0; j < F/4; j++) {
        float4 v;
        v.x = sf[j*4+0] * invc; v.y = sf[j*4+1] * invc;
        v.z = sf[j*4+2] * invc; v.w = sf[j*4+3] * invc;
        fo[j] = v;
    }
}

extern "C" void kernel_launch(void* const* d_in, const int* in_sizes, int n_in,
                              void* d_out, int out_size) {
    // d_in[0] = grid_coords (unused; recomputed analytically)
    const float* means  = (const float*)d_in[1];  // (1, 128, 3)
    const float* opac   = (const float*)d_in[2];  // (1, 128, 1)
    const float* feats  = (const float*)d_in[3];  // (1, 128, 16)
    const float* covs   = (const float*)d_in[4];  // (1, 128, 3, 3)
    float* out = (float*)d_out;                   // [dens 80000 | feats 80000*16]

    dim3 gridDim(NX / TX, NY / TY);   // (25, 20) = 500 blocks, 160 thr each
    fused_splat_kernel<<<gridDim, TPB>>>(means, opac, feats, covs, out);
}

// round 16
// speedup vs baseline: 1.7786x; 1.0295x over previous
#include <cuda_runtime.h>

#define G     128
#define F     16
#define NX    100
#define NY    100
#define NZ    8
#define NPTS  (NX*NY*NZ)

#define TX    4
#define TY    5
#define TZ    8
#define TPB   (TX*TY*TZ)   // 160

__global__ __launch_bounds__(TPB)
void fused_splat_kernel(const float* __restrict__ means,
                        const float* __restrict__ opac,
                        const float* __restrict__ feats,
                        const float* __restrict__ covs,
                        float* __restrict__ out) {
    // Segmented survivor storage: warp w owns slots [w*32, w*32+32)
    __shared__ float4 s_a[G];        // mx, my, mz, opac
    __shared__ float4 s_q[G];        // i00, i01, i02, i11
    __shared__ float2 s_r[G];        // i12, i22
    __shared__ float4 s_of[G][F/4];  // opac * features
    __shared__ int    s_cnt[4];      // survivors per warp segment

    const int tid = threadIdx.x;
    const int bx  = blockIdx.x;      // 0..24
    const int by  = blockIdx.y;      // 0..19

    const float x0 = (bx*TX + 0.5f) * 0.8f - 40.0f;
    const float x1 = (bx*TX + TX - 0.5f) * 0.8f - 40.0f;
    const float y0 = (by*TY + 0.5f) * 0.8f - 40.0f;
    const float y1 = (by*TY + TY - 0.5f) * 0.8f - 40.0f;
    const float z0 = 0.5f * 0.8f - 1.0f;
    const float z1 = (NZ - 0.5f) * 0.8f - 1.0f;

    // ── Stage 1: hoisted loads, tile cull, single-barrier segmented compaction ──
    if (tid < G) {
        const float* Cp = covs + tid*9;
        const float m00 = Cp[0], m01 = Cp[1], m02 = Cp[2];
        const float m10 = Cp[3], m11 = Cp[4], m12 = Cp[5];
        const float m20 = Cp[6], m21 = Cp[7], m22 = Cp[8];
        const float mx = means[tid*3 + 0];
        const float my = means[tid*3 + 1];
        const float mz = means[tid*3 + 2];
        const float o  = opac[tid];
        const float4* fr = reinterpret_cast<const float4*>(feats + tid*F);
        const float4 f0 = fr[0], f1 = fr[1], f2 = fr[2], f3 = fr[3];

        const float hwx = 2.0f * sqrtf(m00) * 1.0002f + 1e-3f;
        const float hwy = 2.0f * sqrtf(m11) * 1.0002f + 1e-3f;
        const float hwz = 2.0f * sqrtf(m22) * 1.0002f + 1e-3f;
        const float dxm = fabsf(fminf(fmaxf(mx, x0), x1) - mx);
        const float dym = fabsf(fminf(fmaxf(my, y0), y1) - my);
        const float dzm = fabsf(fminf(fmaxf(mz, z0), z1) - mz);
        const bool keep = (dxm <= hwx) && (dym <= hwy) && (dzm <= hwz);

        const int w = tid >> 5, lane = tid & 31;
        const unsigned m = __ballot_sync(0xffffffffu, keep);
        if (lane == 0) s_cnt[w] = __popc(m);

        if (keep) {
            const int k = w*32 + __popc(m & ((1u << lane) - 1u));

            // fp32 adjugate + Newton-refined reciprocal det
            const float A00 = m11*m22 - m12*m21;
            const float A01 = m02*m21 - m01*m22;
            const float A02 = m01*m12 - m02*m11;
            const float A10 = m12*m20 - m10*m22;
            const float A11 = m00*m22 - m02*m20;
            const float A12 = m02*m10 - m00*m12;
            const float A20 = m10*m21 - m11*m20;
            const float A21 = m01*m20 - m00*m21;
            const float A22 = m00*m11 - m01*m10;
            const float det = m00*A00 + m01*A10 + m02*A20;
            float r = __fdividef(1.0f, det);
            r = fmaf(r, fmaf(-det, r, 1.0f), r);

            // symmetric X0
            const float x00 = A00 * r;
            const float x01 = 0.5f * (A01 + A10) * r;
            const float x02 = 0.5f * (A02 + A20) * r;
            const float x11 = A11 * r;
            const float x12 = 0.5f * (A12 + A21) * r;
            const float x22 = A22 * r;

            // One Newton step: X1 = 2*X0 - X0*(C*X0), symmetrized
            const float M00 = m00*x00 + m01*x01 + m02*x02;
            const float M01 = m00*x01 + m01*x11 + m02*x12;
            const float M02 = m00*x02 + m01*x12 + m02*x22;
            const float M10 = m10*x00 + m11*x01 + m12*x02;
            const float M11 = m10*x01 + m11*x11 + m12*x12;
            const float M12 = m10*x02 + m11*x12 + m12*x22;
            const float M20 = m20*x00 + m21*x01 + m22*x02;
            const float M21 = m20*x01 + m21*x11 + m22*x12;
            const float M22 = m20*x02 + m21*x12 + m22*x22;
            const float T00 = x00*M00 + x01*M10 + x02*M20;
            const float T01 = x00*M01 + x01*M11 + x02*M21;
            const float T02 = x00*M02 + x01*M12 + x02*M22;
            const float T10 = x01*M00 + x11*M10 + x12*M20;
            const float T11 = x01*M01 + x11*M11 + x12*M21;
            const float T12 = x01*M02 + x11*M12 + x12*M22;
            const float T20 = x02*M00 + x12*M10 + x22*M20;
            const float T21 = x02*M01 + x12*M11 + x22*M21;
            const float T22 = x02*M02 + x12*M12 + x22*M22;

            const float i00 = 2.0f*x00 - T00;
            const float i01 = 2.0f*x01 - 0.5f*(T01 + T10);
            const float i02 = 2.0f*x02 - 0.5f*(T02 + T20);
            const float i11 = 2.0f*x11 - T11;
            const float i12 = 2.0f*x12 - 0.5f*(T12 + T21);
            const float i22 = 2.0f*x22 - T22;

            s_a[k] = make_float4(mx, my, mz, o);
            s_q[k] = make_float4(i00, i01, i02, i11);
            s_r[k] = make_float2(i12, i22);
            s_of[k][0] = make_float4(o*f0.x, o*f0.y, o*f0.z, o*f0.w);
            s_of[k][1] = make_float4(o*f1.x, o*f1.y, o*f1.z, o*f1.w);
            s_of[k][2] = make_float4(o*f2.x, o*f2.y, o*f2.z, o*f2.w);
            s_of[k][3] = make_float4(o*f3.x, o*f3.y, o*f3.z, o*f3.w);
        }
    }
    __syncthreads();   // the only barrier

    // ── Stage 2: one voxel per thread, branchless inner loop ──
    const int tz = tid & (TZ - 1);
    const int ty = (tid / TZ) % TY;
    const int tx = tid / (TZ * TY);
    const int x = bx*TX + tx;
    const int y = by*TY + ty;
    const int z = tz;
    const int n = (x * NY + y) * NZ + z;

    const float px = __fadd_rn(__fmul_rn((float)x + 0.5f, 0.8f), -40.0f);
    const float py = __fadd_rn(__fmul_rn((float)y + 0.5f, 0.8f), -40.0f);
    const float pz = __fadd_rn(__fmul_rn((float)z + 0.5f, 0.8f), -1.0f);

    float sum_d = 0.0f, cnt = 0.0f;
    float sf[F];
    #pragma unroll
    for (int j = 0; j < F; j++) sf[j] = 0.0f;

    #pragma unroll
    for (int w = 0; w < 4; w++) {
        const int e = s_cnt[w];
        for (int j = 0; j < e; j++) {
            const int k = w*32 + j;
            const float4 a = s_a[k];
            const float4 q = s_q[k];
            const float2 rr = s_r[k];
            const float dx = px - a.x;
            const float dy = py - a.y;
            const float dz = pz - a.z;

            // exact mask: maha <= 4 (no early-outs, no branches)
            const float maha = q.x*dx*dx + q.w*dy*dy + rr.y*dz*dz
                             + 2.0f * (q.y*dx*dy + q.z*dx*dz + rr.x*dy*dz);
            const bool hit = (maha <= 4.0f);
            const float wg = hit ? __expf(-0.5f * maha) : 0.0f;  // exact 0 on miss
            cnt   += hit ? 1.0f : 0.0f;
            sum_d  = fmaf(a.w, wg, sum_d);
            #pragma unroll
            for (int p = 0; p < F/4; p++) {
                const float4 of = s_of[k][p];
                sf[p*4+0] = fmaf(of.x, wg, sf[p*4+0]);
                sf[p*4+1] = fmaf(of.y, wg, sf[p*4+1]);
                sf[p*4+2] = fmaf(of.z, wg, sf[p*4+2]);
                sf[p*4+3] = fmaf(of.w, wg, sf[p*4+3]);
            }
        }
    }

    const float invc = (cnt > 0.0f) ? (1.0f / cnt) : 0.0f;
    out[n] = sum_d * invc;

    float4* fo = reinterpret_cast<float4*>(out + NPTS + (size_t)n * F);
    #pragma unroll
    for (int j = 0; j < F/4; j++) {
        float4 v;
        v.x = sf[j*4+0] * invc; v.y = sf[j*4+1] * invc;
        v.z = sf[j*4+2] * invc; v.w = sf[j*4+3] * invc;
        fo[j] = v;
    }
}

extern "C" void kernel_launch(void* const* d_in, const int* in_sizes, int n_in,
                              void* d_out, int out_size) {
    // d_in[0] = grid_coords (unused; recomputed analytically)
    const float* means  = (const float*)d_in[1];  // (1, 128, 3)
    const float* opac   = (const float*)d_in[2];  // (1, 128, 1)
    const float* feats  = (const float*)d_in[3];  // (1, 128, 16)
    const float* covs   = (const float*)d_in[4];  // (1, 128, 3, 3)
    float* out = (float*)d_out;                   // [dens 80000 | feats 80000*16]

    dim3 gridDim(NX / TX, NY / TY);   // (25, 20) = 500 blocks, 160 thr each
    fused_splat_kernel<<<gridDim, TPB>>>(means, opac, feats, covs, out);
}